// round 1
// baseline (speedup 1.0000x reference)
#include <cuda_runtime.h>

// Problem constants
#define BB  2
#define SS  2048
#define DD  1024
#define HH  1024
#define NHH 16
#define DHH 64

// ---------------------------------------------------------------------------
// Static device scratch (no runtime allocation allowed).
//   g_Kp/g_Qp/g_Vp : head-major projections [B, nh, S, dh]   (16 MB each)
//   g_score        : [B, nh, S(i), S(k)] scores then attn    (512 MB)
//   g_X            : pre-output-projection activations [B,S,H] (16 MB)
// ---------------------------------------------------------------------------
__device__ float g_Kp[BB * NHH * SS * DHH];
__device__ float g_Qp[BB * NHH * SS * DHH];
__device__ float g_Vp[BB * NHH * SS * DHH];
__device__ float g_score[(size_t)BB * NHH * SS * SS];
__device__ float g_X[BB * SS * HH];

// ---------------------------------------------------------------------------
// Kernel 1: input projection  P = A @ W^T + b, stored head-major.
//   A: [B*S, D] row-major, W: [H, D] row-major.
//   Output channel c -> head n = c % 16, dim d = c / 16:
//   out[((b*16 + n)*S + s)*64 + d]
// 128x128x16 tile, 256 threads, 8x8 per thread.
// ---------------------------------------------------------------------------
__global__ void __launch_bounds__(256) proj_kernel(const float* __restrict__ A,
                                                   const float* __restrict__ W,
                                                   const float* __restrict__ bias,
                                                   int which)
{
    float* out = (which == 0) ? g_Kp : (which == 1) ? g_Qp : g_Vp;

    __shared__ float As[16][132];
    __shared__ float Bs[16][132];

    const int bm = blockIdx.y * 128;
    const int bn = blockIdx.x * 128;
    const int tid = threadIdx.x;
    const int tx = tid & 15;
    const int ty = tid >> 4;

    float acc[8][8];
#pragma unroll
    for (int i = 0; i < 8; i++)
#pragma unroll
        for (int j = 0; j < 8; j++) acc[i][j] = 0.f;

    for (int k0 = 0; k0 < DD; k0 += 16) {
#pragma unroll
        for (int l = 0; l < 2; l++) {
            int f = tid + l * 256;
            int row = f >> 2;
            int c4 = (f & 3) << 2;
            float4 va = *(const float4*)(&A[(size_t)(bm + row) * DD + k0 + c4]);
            As[c4 + 0][row] = va.x; As[c4 + 1][row] = va.y;
            As[c4 + 2][row] = va.z; As[c4 + 3][row] = va.w;
            float4 vb = *(const float4*)(&W[(size_t)(bn + row) * DD + k0 + c4]);
            Bs[c4 + 0][row] = vb.x; Bs[c4 + 1][row] = vb.y;
            Bs[c4 + 2][row] = vb.z; Bs[c4 + 3][row] = vb.w;
        }
        __syncthreads();

#pragma unroll
        for (int kk = 0; kk < 16; kk++) {
            float a[8], b[8];
            *(float4*)&a[0] = *(float4*)&As[kk][ty * 8];
            *(float4*)&a[4] = *(float4*)&As[kk][ty * 8 + 4];
            *(float4*)&b[0] = *(float4*)&Bs[kk][tx * 8];
            *(float4*)&b[4] = *(float4*)&Bs[kk][tx * 8 + 4];
#pragma unroll
            for (int i = 0; i < 8; i++)
#pragma unroll
                for (int j = 0; j < 8; j++)
                    acc[i][j] += a[i] * b[j];
        }
        __syncthreads();
    }

#pragma unroll
    for (int j = 0; j < 8; j++) {
        int c = bn + tx * 8 + j;
        float bv = bias[c];
        int n = c & 15;
        int dcol = c >> 4;
#pragma unroll
        for (int i = 0; i < 8; i++) {
            int m = bm + ty * 8 + i;
            int b_ = m >> 11;
            int s = m & 2047;
            out[((size_t)(b_ * NHH + n) * SS + s) * DHH + dcol] = acc[i][j] + bv;
        }
    }
}

// ---------------------------------------------------------------------------
// Kernel 2: score[b,h,i,k] = (1/8) * dot(Kp[b,h,i,:], Qp[b,h,k,:])
// Batched over z = b*16 + h. M=N=2048, K=64.
// ---------------------------------------------------------------------------
__global__ void __launch_bounds__(256) score_kernel()
{
    const int bh = blockIdx.z;
    const float* Ap = g_Kp + (size_t)bh * SS * DHH;
    const float* Bp = g_Qp + (size_t)bh * SS * DHH;
    float* out = g_score + (size_t)bh * SS * SS;

    __shared__ float As[16][132];
    __shared__ float Bs[16][132];

    const int bm = blockIdx.y * 128;   // i
    const int bn = blockIdx.x * 128;   // k
    const int tid = threadIdx.x;
    const int tx = tid & 15;
    const int ty = tid >> 4;

    float acc[8][8];
#pragma unroll
    for (int i = 0; i < 8; i++)
#pragma unroll
        for (int j = 0; j < 8; j++) acc[i][j] = 0.f;

    for (int k0 = 0; k0 < DHH; k0 += 16) {
#pragma unroll
        for (int l = 0; l < 2; l++) {
            int f = tid + l * 256;
            int row = f >> 2;
            int c4 = (f & 3) << 2;
            float4 va = *(const float4*)(&Ap[(size_t)(bm + row) * DHH + k0 + c4]);
            As[c4 + 0][row] = va.x; As[c4 + 1][row] = va.y;
            As[c4 + 2][row] = va.z; As[c4 + 3][row] = va.w;
            float4 vb = *(const float4*)(&Bp[(size_t)(bn + row) * DHH + k0 + c4]);
            Bs[c4 + 0][row] = vb.x; Bs[c4 + 1][row] = vb.y;
            Bs[c4 + 2][row] = vb.z; Bs[c4 + 3][row] = vb.w;
        }
        __syncthreads();

#pragma unroll
        for (int kk = 0; kk < 16; kk++) {
            float a[8], b[8];
            *(float4*)&a[0] = *(float4*)&As[kk][ty * 8];
            *(float4*)&a[4] = *(float4*)&As[kk][ty * 8 + 4];
            *(float4*)&b[0] = *(float4*)&Bs[kk][tx * 8];
            *(float4*)&b[4] = *(float4*)&Bs[kk][tx * 8 + 4];
#pragma unroll
            for (int i = 0; i < 8; i++)
#pragma unroll
                for (int j = 0; j < 8; j++)
                    acc[i][j] += a[i] * b[j];
        }
        __syncthreads();
    }

#pragma unroll
    for (int i = 0; i < 8; i++) {
        size_t rowbase = (size_t)(bm + ty * 8 + i) * SS + bn;
#pragma unroll
        for (int j = 0; j < 8; j++)
            out[rowbase + tx * 8 + j] = acc[i][j] * 0.125f;
    }
}

// ---------------------------------------------------------------------------
// Kernel 3: softmax over the HEAD axis (the reference's axis=1 quirk).
// For each (b, i, k): softmax over the 16 values score[b, :, i, k].
// ---------------------------------------------------------------------------
__global__ void __launch_bounds__(256) softmax_kernel()
{
    size_t idx = (size_t)blockIdx.x * 256 + threadIdx.x;   // over B*S*S
    size_t b = idx / ((size_t)SS * SS);
    size_t rem = idx - b * (size_t)SS * SS;                // i*S + k
    size_t base = b * (size_t)NHH * SS * SS + rem;

    float v[NHH];
    float mx = -1e30f;
#pragma unroll
    for (int h = 0; h < NHH; h++) {
        v[h] = g_score[base + (size_t)h * SS * SS];
        mx = fmaxf(mx, v[h]);
    }
    float sum = 0.f;
#pragma unroll
    for (int h = 0; h < NHH; h++) {
        v[h] = __expf(v[h] - mx);
        sum += v[h];
    }
    float inv = 1.f / sum;
#pragma unroll
    for (int h = 0; h < NHH; h++)
        g_score[base + (size_t)h * SS * SS] = v[h] * inv;
}

// ---------------------------------------------------------------------------
// Kernel 4: O[b,h,j,k] = sum_i attn[b,h,i,k] * Vp[b,h,i,j]
// Written directly in final pre-Wo layout: X[b, k, j*16 + h].
// Per (b,h): C[k, j] with k=2048 (M), j=64 (N), i=2048 (reduction).
// Tile 128(k) x 64(j) x 16(i); 256 threads, 8x4 per thread.
// ---------------------------------------------------------------------------
__global__ void __launch_bounds__(256) av_kernel()
{
    const int bh = blockIdx.z;
    const int b_ = bh >> 4;
    const int n = bh & 15;
    const float* attn = g_score + (size_t)bh * SS * SS;   // [i][k]
    const float* V = g_Vp + (size_t)bh * SS * DHH;        // [i][j]

    __shared__ float As[16][128];   // [i][k-tile]
    __shared__ float Bs[16][64];    // [i][j]

    const int bm = blockIdx.x * 128;   // k offset
    const int tid = threadIdx.x;
    const int tx = tid & 15;
    const int ty = tid >> 4;

    float acc[8][4];
#pragma unroll
    for (int i = 0; i < 8; i++)
#pragma unroll
        for (int j = 0; j < 4; j++) acc[i][j] = 0.f;

    for (int i0 = 0; i0 < SS; i0 += 16) {
#pragma unroll
        for (int l = 0; l < 2; l++) {
            int f = tid + l * 256;
            int row = f >> 5;          // 0..15
            int c4 = (f & 31) << 2;    // 0..124
            *(float4*)&As[row][c4] =
                *(const float4*)&attn[(size_t)(i0 + row) * SS + bm + c4];
        }
        {
            int row = tid >> 4;        // 0..15
            int c4 = (tid & 15) << 2;  // 0..60
            *(float4*)&Bs[row][c4] =
                *(const float4*)&V[(size_t)(i0 + row) * DHH + c4];
        }
        __syncthreads();

#pragma unroll
        for (int kk = 0; kk < 16; kk++) {
            float a[8], bv[4];
            *(float4*)&a[0] = *(float4*)&As[kk][ty * 8];
            *(float4*)&a[4] = *(float4*)&As[kk][ty * 8 + 4];
            *(float4*)&bv[0] = *(float4*)&Bs[kk][tx * 4];
#pragma unroll
            for (int i = 0; i < 8; i++)
#pragma unroll
                for (int j = 0; j < 4; j++)
                    acc[i][j] += a[i] * bv[j];
        }
        __syncthreads();
    }

#pragma unroll
    for (int i = 0; i < 8; i++) {
        int kq = bm + ty * 8 + i;
        float* xrow = g_X + ((size_t)b_ * SS + kq) * HH;
#pragma unroll
        for (int jj = 0; jj < 4; jj++) {
            int j = tx * 4 + jj;
            xrow[j * 16 + n] = acc[i][jj];
        }
    }
}

// ---------------------------------------------------------------------------
// Kernel 5: output projection  res = X @ Wo^T + Wo_b
// ---------------------------------------------------------------------------
__global__ void __launch_bounds__(256) outproj_kernel(const float* __restrict__ Wo,
                                                      const float* __restrict__ bias,
                                                      float* __restrict__ out)
{
    const float* A = g_X;

    __shared__ float As[16][132];
    __shared__ float Bs[16][132];

    const int bm = blockIdx.y * 128;
    const int bn = blockIdx.x * 128;
    const int tid = threadIdx.x;
    const int tx = tid & 15;
    const int ty = tid >> 4;

    float acc[8][8];
#pragma unroll
    for (int i = 0; i < 8; i++)
#pragma unroll
        for (int j = 0; j < 8; j++) acc[i][j] = 0.f;

    for (int k0 = 0; k0 < HH; k0 += 16) {
#pragma unroll
        for (int l = 0; l < 2; l++) {
            int f = tid + l * 256;
            int row = f >> 2;
            int c4 = (f & 3) << 2;
            float4 va = *(const float4*)(&A[(size_t)(bm + row) * HH + k0 + c4]);
            As[c4 + 0][row] = va.x; As[c4 + 1][row] = va.y;
            As[c4 + 2][row] = va.z; As[c4 + 3][row] = va.w;
            float4 vb = *(const float4*)(&Wo[(size_t)(bn + row) * HH + k0 + c4]);
            Bs[c4 + 0][row] = vb.x; Bs[c4 + 1][row] = vb.y;
            Bs[c4 + 2][row] = vb.z; Bs[c4 + 3][row] = vb.w;
        }
        __syncthreads();

#pragma unroll
        for (int kk = 0; kk < 16; kk++) {
            float a[8], b[8];
            *(float4*)&a[0] = *(float4*)&As[kk][ty * 8];
            *(float4*)&a[4] = *(float4*)&As[kk][ty * 8 + 4];
            *(float4*)&b[0] = *(float4*)&Bs[kk][tx * 8];
            *(float4*)&b[4] = *(float4*)&Bs[kk][tx * 8 + 4];
#pragma unroll
            for (int i = 0; i < 8; i++)
#pragma unroll
                for (int j = 0; j < 8; j++)
                    acc[i][j] += a[i] * b[j];
        }
        __syncthreads();
    }

#pragma unroll
    for (int j = 0; j < 8; j++) {
        int c = bn + tx * 8 + j;
        float bv = bias[c];
#pragma unroll
        for (int i = 0; i < 8; i++) {
            int m = bm + ty * 8 + i;
            out[(size_t)m * HH + c] = acc[i][j] + bv;
        }
    }
}

// ---------------------------------------------------------------------------
// Launch
// ---------------------------------------------------------------------------
extern "C" void kernel_launch(void* const* d_in, const int* in_sizes, int n_in,
                              void* d_out, int out_size)
{
    const float* KEY   = (const float*)d_in[0];
    const float* VALUE = (const float*)d_in[1];
    const float* QUERY = (const float*)d_in[2];
    const float* Wk_w  = (const float*)d_in[3];
    const float* Wk_b  = (const float*)d_in[4];
    const float* Wq_w  = (const float*)d_in[5];
    const float* Wq_b  = (const float*)d_in[6];
    const float* Wv_w  = (const float*)d_in[7];
    const float* Wv_b  = (const float*)d_in[8];
    const float* Wo_w  = (const float*)d_in[9];
    const float* Wo_b  = (const float*)d_in[10];
    float* out = (float*)d_out;

    dim3 pg(HH / 128, (BB * SS) / 128);          // (8, 32)
    proj_kernel<<<pg, 256>>>(KEY,   Wk_w, Wk_b, 0);
    proj_kernel<<<pg, 256>>>(QUERY, Wq_w, Wq_b, 1);
    proj_kernel<<<pg, 256>>>(VALUE, Wv_w, Wv_b, 2);

    dim3 sg(SS / 128, SS / 128, BB * NHH);       // (16, 16, 32)
    score_kernel<<<sg, 256>>>();

    softmax_kernel<<<(BB * SS * SS) / 256, 256>>>();   // 32768 blocks

    dim3 ag(SS / 128, 1, BB * NHH);              // (16, 1, 32)
    av_kernel<<<ag, 256>>>();

    dim3 og(HH / 128, (BB * SS) / 128);          // (8, 32)
    outproj_kernel<<<og, 256>>>(Wo_w, Wo_b, out);
}